// round 1
// baseline (speedup 1.0000x reference)
#include <cuda_runtime.h>
#include <cstdint>

// ---------------------------------------------------------------------------
// TFN forward:
//   a1/v1/t1 = [1, relu(x @ W + b)]            (B=64, H=96 -> 97 cols each)
//   y1 = relu( einsum('ba,bv,bt->b(avt)') @ W1 + b1 )   <-- 350 MB W1, dominant
//   features = relu(y1 @ W2 + b2)
//   heads: features @ Wo{1,2,3} + bo{1,2,3};  interloss = 0
//
// Strategy: never materialize fusion. For W1 row r = a*9409 + v*97 + t:
//   coeff[b,r] = (a1[b,a]*v1[b,v]) * t1[b,t] = m[b] * t1[b,t]
// Main GEMM done with mma.sync m16n8k8 tf32; t1 fragments live in registers
// for the whole kernel; m[b] is folded into the A fragment per 97-row chunk.
// W1 streamed once through double-buffered smem (stride 104 -> conflict-free
// B-fragment LDS). K split over 152 CTAs; partials reduced in a tail kernel.
// ---------------------------------------------------------------------------

#define NBLK   152
#define CHUNKS 9409          // 97*97 (a,v) pairs
#define BDIM   64
#define HDIM   96
#define LDSW   104           // smem row stride in floats
#define WBUF   (LDSW * 104)  // one W1 chunk buffer (104 rows x 104 floats)
#define SMEM_FLOATS (2*WBUF + 2*6208)

__device__ float g_a1[BDIM * 97];
__device__ float g_v1[BDIM * 97];
__device__ float g_t1[BDIM * 97];
__device__ float g_part[NBLK * BDIM * HDIM];

// ---------------------------------------------------------------------------

__device__ __forceinline__ float f2tf32f(float x) {
    uint32_t r;
    asm("cvt.rna.tf32.f32 %0, %1;" : "=r"(r) : "f"(x));
    return __uint_as_float(r);
}
__device__ __forceinline__ uint32_t f2tf32u(float x) {
    uint32_t r;
    asm("cvt.rna.tf32.f32 %0, %1;" : "=r"(r) : "f"(x));
    return r;
}

__device__ __forceinline__ void mma_tf32(float c[4],
                                         uint32_t a0, uint32_t a1,
                                         uint32_t a2, uint32_t a3,
                                         uint32_t b0, uint32_t b1) {
    asm volatile(
        "mma.sync.aligned.m16n8k8.row.col.f32.tf32.tf32.f32 "
        "{%0,%1,%2,%3}, {%4,%5,%6,%7}, {%8,%9}, {%0,%1,%2,%3};"
        : "+f"(c[0]), "+f"(c[1]), "+f"(c[2]), "+f"(c[3])
        : "r"(a0), "r"(a1), "r"(a2), "r"(a3), "r"(b0), "r"(b1));
}

// 97*96 = 9312 floats = 2328 float4 per chunk. 256 threads: 9 each + 24 extra.
__device__ __forceinline__ void stage_ldg(float4* stg,
                                          const float* __restrict__ W1,
                                          int av, int tid) {
    const float4* src = reinterpret_cast<const float4*>(W1 + (size_t)av * 9312);
#pragma unroll
    for (int j = 0; j < 9; j++) stg[j] = src[tid + j * 256];
    if (tid < 24) stg[9] = src[2304 + tid];
}

__device__ __forceinline__ void stage_sts(float* buf, const float4* stg, int tid) {
#pragma unroll
    for (int j = 0; j < 9; j++) {
        int q = tid + j * 256;
        int e = q * 4;
        int t = e / 96;
        int c = e - t * 96;
        float4 v = stg[j], o;
        o.x = f2tf32f(v.x); o.y = f2tf32f(v.y);
        o.z = f2tf32f(v.z); o.w = f2tf32f(v.w);
        *reinterpret_cast<float4*>(buf + t * LDSW + c) = o;
    }
    if (tid < 24) {
        int q = 2304 + tid;
        int e = q * 4;
        int t = e / 96;
        int c = e - t * 96;
        float4 v = stg[9], o;
        o.x = f2tf32f(v.x); o.y = f2tf32f(v.y);
        o.z = f2tf32f(v.z); o.w = f2tf32f(v.w);
        *reinterpret_cast<float4*>(buf + t * LDSW + c) = o;
    }
}

// ---------------------------------------------------------------------------
// Kernel 1: the three MLP encoders -> g_a1 / g_t1 / g_v1 with leading ones col
// ---------------------------------------------------------------------------
__global__ void __launch_bounds__(96) tfn_enc(
    const float* __restrict__ audios, const float* __restrict__ texts,
    const float* __restrict__ videos,
    const float* __restrict__ Wa, const float* __restrict__ ba,
    const float* __restrict__ Wt, const float* __restrict__ bt,
    const float* __restrict__ Wv, const float* __restrict__ bv) {
    int b = blockIdx.x;
    int mod = blockIdx.y;
    int h = threadIdx.x;

    const float* x; const float* W; const float* bias; float* out; int K;
    if (mod == 0)      { x = audios; W = Wa; bias = ba; out = g_a1; K = 512; }
    else if (mod == 1) { x = texts;  W = Wt; bias = bt; out = g_t1; K = 1024; }
    else               { x = videos; W = Wv; bias = bv; out = g_v1; K = 512; }

    const float* xb = x + (size_t)b * K;
    float a0 = 0.f, a1 = 0.f, a2 = 0.f, a3 = 0.f;
    for (int k = 0; k < K; k += 4) {
        a0 += xb[k + 0] * W[(k + 0) * HDIM + h];
        a1 += xb[k + 1] * W[(k + 1) * HDIM + h];
        a2 += xb[k + 2] * W[(k + 2) * HDIM + h];
        a3 += xb[k + 3] * W[(k + 3) * HDIM + h];
    }
    float acc = bias[h] + ((a0 + a1) + (a2 + a3));
    out[b * 97 + 1 + h] = fmaxf(acc, 0.f);
    if (h == 0) out[b * 97] = 1.f;
}

// ---------------------------------------------------------------------------
// Kernel 2: main fused trilinear GEMM (y1 partials, pre-bias/relu)
//   grid = 152 CTAs x 256 threads, 1 CTA/SM, dynamic smem 136 KB
// ---------------------------------------------------------------------------
__global__ void __launch_bounds__(256, 1) tfn_main(const float* __restrict__ W1) {
    extern __shared__ float sm[];
    float* wb0 = sm;
    float* wb1 = sm + WBUF;
    float* a1s = sm + 2 * WBUF;
    float* v1s = a1s + 6208;

    const int tid  = threadIdx.x;
    const int lane = tid & 31;
    const int wid  = tid >> 5;
    const int wm   = wid & 3;    // m-warp: rows 16*wm..16*wm+15 (+8 group)
    const int wn   = wid >> 2;   // n-warp: cols 48*wn..48*wn+47
    const int gid  = lane >> 2;
    const int tig  = lane & 3;
    const int b0   = wm * 16 + gid;
    const int nbase = wn * 48;

    for (int i = tid; i < 6208; i += 256) { a1s[i] = g_a1[i]; v1s[i] = g_v1[i]; }
    // zero pad rows 97..103 of both buffers (k-tail reads them; t1 frag there = 0)
    for (int i = tid; i < 7 * LDSW; i += 256) {
        wb0[97 * LDSW + i] = 0.f;
        wb1[97 * LDSW + i] = 0.f;
    }

    // persistent t1 A-fragments (13 k-steps of 8 covering t = 0..96, padded)
    float t1f[13][4];
#pragma unroll
    for (int ks = 0; ks < 13; ks++) {
        int ta = ks * 8 + tig;
        int tb = ta + 4;
        t1f[ks][0] = (ta < 97) ? g_t1[b0 * 97 + ta] : 0.f;
        t1f[ks][1] = (ta < 97) ? g_t1[(b0 + 8) * 97 + ta] : 0.f;
        t1f[ks][2] = (tb < 97) ? g_t1[b0 * 97 + tb] : 0.f;
        t1f[ks][3] = (tb < 97) ? g_t1[(b0 + 8) * 97 + tb] : 0.f;
    }

    float Y[6][4];
#pragma unroll
    for (int j = 0; j < 6; j++) { Y[j][0] = Y[j][1] = Y[j][2] = Y[j][3] = 0.f; }

    const int bk = blockIdx.x;
    // 9409 = 152*61 + 137 : first 137 blocks take 62 chunks
    const int cstart = (bk < 137) ? bk * 62 : bk * 61 + 137;
    const int ccnt   = (bk < 137) ? 62 : 61;

    float4 stg[10];
    // prologue
    stage_ldg(stg, W1, cstart, tid);
    stage_sts(wb0, stg, tid);
    __syncthreads();

    for (int ci = 0; ci < ccnt; ci++) {
        const float* cur = (ci & 1) ? wb1 : wb0;
        float* nxt       = (ci & 1) ? wb0 : wb1;
        const int av = cstart + ci;
        const bool hn = (ci + 1 < ccnt);

        if (hn) stage_ldg(stg, W1, av + 1, tid);   // overlap with compute

        const int ca = av / 97;
        const int cv = av - ca * 97;
        const float m0r = a1s[b0 * 97 + ca] * v1s[b0 * 97 + cv];
        const float m1r = a1s[(b0 + 8) * 97 + ca] * v1s[(b0 + 8) * 97 + cv];

#pragma unroll
        for (int ks = 0; ks < 13; ks++) {
            const uint32_t A0 = f2tf32u(m0r * t1f[ks][0]);
            const uint32_t A1 = f2tf32u(m1r * t1f[ks][1]);
            const uint32_t A2 = f2tf32u(m0r * t1f[ks][2]);
            const uint32_t A3 = f2tf32u(m1r * t1f[ks][3]);
            const float* bp  = cur + (ks * 8 + tig) * LDSW + nbase + gid;
            const float* bp4 = bp + 4 * LDSW;
#pragma unroll
            for (int j = 0; j < 6; j++) {
                uint32_t B0 = __float_as_uint(bp[8 * j]);
                uint32_t B1 = __float_as_uint(bp4[8 * j]);
                mma_tf32(Y[j], A0, A1, A2, A3, B0, B1);
            }
        }

        if (hn) stage_sts(nxt, stg, tid);
        __syncthreads();
    }

    // write fp32 partials [bk][b][h]
    float* dst = g_part + (size_t)bk * (BDIM * HDIM);
#pragma unroll
    for (int j = 0; j < 6; j++) {
        int h = nbase + 8 * j + 2 * tig;
        *reinterpret_cast<float2*>(dst + b0 * HDIM + h) =
            make_float2(Y[j][0], Y[j][1]);
        *reinterpret_cast<float2*>(dst + (b0 + 8) * HDIM + h) =
            make_float2(Y[j][2], Y[j][3]);
    }
}

// ---------------------------------------------------------------------------
// Kernel 3: reduce partials + bias/relu + W2 + heads. One block per batch row.
// out layout: features[64*96] | emos[64*6] | vals[64*1] | sents[64*3] | interloss
// ---------------------------------------------------------------------------
__global__ void __launch_bounds__(96) tfn_tail(
    const float* __restrict__ b1, const float* __restrict__ W2,
    const float* __restrict__ b2,
    const float* __restrict__ Wo1, const float* __restrict__ bo1,
    const float* __restrict__ Wo2, const float* __restrict__ bo2,
    const float* __restrict__ Wo3, const float* __restrict__ bo3,
    float* __restrict__ out) {
    __shared__ float yr[HDIM];
    __shared__ float fs[HDIM];
    const int b = blockIdx.x;
    const int h = threadIdx.x;

    float acc = b1[h];
#pragma unroll 8
    for (int p = 0; p < NBLK; p++)
        acc += g_part[(size_t)p * (BDIM * HDIM) + b * HDIM + h];
    yr[h] = fmaxf(acc, 0.f);
    __syncthreads();

    float f = b2[h];
#pragma unroll 8
    for (int k = 0; k < HDIM; k++) f += yr[k] * W2[k * HDIM + h];
    f = fmaxf(f, 0.f);
    fs[h] = f;
    out[b * HDIM + h] = f;
    __syncthreads();

    if (h < 6) {
        float a = bo1[h];
        for (int k = 0; k < HDIM; k++) a += fs[k] * Wo1[k * 6 + h];
        out[6144 + b * 6 + h] = a;
    } else if (h == 6) {
        float a = bo2[0];
        for (int k = 0; k < HDIM; k++) a += fs[k] * Wo2[k];
        out[6528 + b] = a;
    } else if (h < 10) {
        int o = h - 7;
        float a = bo3[o];
        for (int k = 0; k < HDIM; k++) a += fs[k] * Wo3[k * 3 + o];
        out[6592 + b * 3 + o] = a;
    }
    if (b == 0 && h == 95) out[6784] = 0.f;  // interloss
}

// ---------------------------------------------------------------------------

extern "C" void kernel_launch(void* const* d_in, const int* in_sizes, int n_in,
                              void* d_out, int out_size) {
    (void)in_sizes; (void)n_in; (void)out_size;
    const float* audios = (const float*)d_in[0];
    const float* texts  = (const float*)d_in[1];
    const float* videos = (const float*)d_in[2];
    const float* Wa  = (const float*)d_in[3];
    const float* ba  = (const float*)d_in[4];
    const float* Wt  = (const float*)d_in[5];
    const float* bt  = (const float*)d_in[6];
    const float* Wv  = (const float*)d_in[7];
    const float* bv  = (const float*)d_in[8];
    const float* W1  = (const float*)d_in[9];
    const float* b1  = (const float*)d_in[10];
    const float* W2  = (const float*)d_in[11];
    const float* b2  = (const float*)d_in[12];
    const float* Wo1 = (const float*)d_in[13];
    const float* bo1 = (const float*)d_in[14];
    const float* Wo2 = (const float*)d_in[15];
    const float* bo2 = (const float*)d_in[16];
    const float* Wo3 = (const float*)d_in[17];
    const float* bo3 = (const float*)d_in[18];
    float* out = (float*)d_out;

    cudaFuncSetAttribute(tfn_main, cudaFuncAttributeMaxDynamicSharedMemorySize,
                         SMEM_FLOATS * 4);

    tfn_enc<<<dim3(64, 3), 96>>>(audios, texts, videos, Wa, ba, Wt, bt, Wv, bv);
    tfn_main<<<NBLK, 256, SMEM_FLOATS * 4>>>(W1);
    tfn_tail<<<64, 96>>>(b1, W2, b2, Wo1, bo1, Wo2, bo2, Wo3, bo3, out);
}

// round 2
// speedup vs baseline: 1.4059x; 1.4059x over previous
#include <cuda_runtime.h>
#include <cstdint>

// ---------------------------------------------------------------------------
// TFN forward:
//   a1/v1/t1 = [1, relu(x @ W + b)]            (B=64, H=96 -> 97 cols each)
//   y1 = relu( einsum('ba,bv,bt->b(avt)') @ W1 + b1 )   <-- 350 MB W1, dominant
//   features = relu(y1 @ W2 + b2)
//   heads: features @ Wo{1,2,3} + bo{1,2,3};  interloss = 0
//
// R2 changes: enc + tail were latency-bound (enc measured 83.6us, occ 5.5%,
// issue 2.4%). Both rewritten with K-split-per-block + smem reduce (384 thr).
// Main trilinear GEMM kernel unchanged from R1 (passing, rel_err 3.7e-4).
// ---------------------------------------------------------------------------

#define NBLK   152
#define CHUNKS 9409          // 97*97 (a,v) pairs
#define BDIM   64
#define HDIM   96
#define LDSW   104           // smem row stride in floats
#define WBUF   (LDSW * 104)  // one W1 chunk buffer (104 rows x 104 floats)
#define SMEM_FLOATS (2*WBUF + 2*6208)

__device__ float g_a1[BDIM * 97];
__device__ float g_v1[BDIM * 97];
__device__ float g_t1[BDIM * 97];
__device__ float g_part[NBLK * BDIM * HDIM];

// ---------------------------------------------------------------------------

__device__ __forceinline__ float f2tf32f(float x) {
    uint32_t r;
    asm("cvt.rna.tf32.f32 %0, %1;" : "=r"(r) : "f"(x));
    return __uint_as_float(r);
}
__device__ __forceinline__ uint32_t f2tf32u(float x) {
    uint32_t r;
    asm("cvt.rna.tf32.f32 %0, %1;" : "=r"(r) : "f"(x));
    return r;
}

__device__ __forceinline__ void mma_tf32(float c[4],
                                         uint32_t a0, uint32_t a1,
                                         uint32_t a2, uint32_t a3,
                                         uint32_t b0, uint32_t b1) {
    asm volatile(
        "mma.sync.aligned.m16n8k8.row.col.f32.tf32.tf32.f32 "
        "{%0,%1,%2,%3}, {%4,%5,%6,%7}, {%8,%9}, {%0,%1,%2,%3};"
        : "+f"(c[0]), "+f"(c[1]), "+f"(c[2]), "+f"(c[3])
        : "r"(a0), "r"(a1), "r"(a2), "r"(a3), "r"(b0), "r"(b1));
}

// 97*96 = 9312 floats = 2328 float4 per chunk. 256 threads: 9 each + 24 extra.
__device__ __forceinline__ void stage_ldg(float4* stg,
                                          const float* __restrict__ W1,
                                          int av, int tid) {
    const float4* src = reinterpret_cast<const float4*>(W1 + (size_t)av * 9312);
#pragma unroll
    for (int j = 0; j < 9; j++) stg[j] = src[tid + j * 256];
    if (tid < 24) stg[9] = src[2304 + tid];
}

__device__ __forceinline__ void stage_sts(float* buf, const float4* stg, int tid) {
#pragma unroll
    for (int j = 0; j < 9; j++) {
        int q = tid + j * 256;
        int e = q * 4;
        int t = e / 96;
        int c = e - t * 96;
        float4 v = stg[j], o;
        o.x = f2tf32f(v.x); o.y = f2tf32f(v.y);
        o.z = f2tf32f(v.z); o.w = f2tf32f(v.w);
        *reinterpret_cast<float4*>(buf + t * LDSW + c) = o;
    }
    if (tid < 24) {
        int q = 2304 + tid;
        int e = q * 4;
        int t = e / 96;
        int c = e - t * 96;
        float4 v = stg[9], o;
        o.x = f2tf32f(v.x); o.y = f2tf32f(v.y);
        o.z = f2tf32f(v.z); o.w = f2tf32f(v.w);
        *reinterpret_cast<float4*>(buf + t * LDSW + c) = o;
    }
}

// ---------------------------------------------------------------------------
// Kernel 1: encoders. grid (64 batch, 3 mods), 384 threads = 96 h x 4 K-slices.
// x row staged in smem; 4 partial dot products reduced through smem.
// ---------------------------------------------------------------------------
__global__ void __launch_bounds__(384) tfn_enc(
    const float* __restrict__ audios, const float* __restrict__ texts,
    const float* __restrict__ videos,
    const float* __restrict__ Wa, const float* __restrict__ ba,
    const float* __restrict__ Wt, const float* __restrict__ bt,
    const float* __restrict__ Wv, const float* __restrict__ bv) {
    const int b   = blockIdx.x;
    const int mod = blockIdx.y;
    const int tid = threadIdx.x;

    const float* x; const float* W; const float* bias; float* out; int K;
    if (mod == 0)      { x = audios; W = Wa; bias = ba; out = g_a1; K = 512; }
    else if (mod == 1) { x = texts;  W = Wt; bias = bt; out = g_t1; K = 1024; }
    else               { x = videos; W = Wv; bias = bv; out = g_v1; K = 512; }

    __shared__ float xs[1024];
    __shared__ float ps[384];

    const float* xb = x + (size_t)b * K;
    for (int i = tid; i < K; i += 384) xs[i] = xb[i];
    __syncthreads();

    const int h  = tid % 96;
    const int g  = tid / 96;           // 0..3
    const int kq = K >> 2;             // 128 or 256
    const int k0 = g * kq;

    float acc = 0.f;
#pragma unroll 8
    for (int k = k0; k < k0 + kq; k++)
        acc += xs[k] * W[k * HDIM + h];
    ps[tid] = acc;
    __syncthreads();

    if (g == 0) {
        float r = bias[h] + ((ps[h] + ps[h + 96]) + (ps[h + 192] + ps[h + 288]));
        out[b * 97 + 1 + h] = fmaxf(r, 0.f);
        if (h == 0) out[b * 97] = 1.f;
    }
}

// ---------------------------------------------------------------------------
// Kernel 2: main fused trilinear GEMM (y1 partials, pre-bias/relu)
//   grid = 152 CTAs x 256 threads, 1 CTA/SM, dynamic smem 136 KB
// ---------------------------------------------------------------------------
__global__ void __launch_bounds__(256, 1) tfn_main(const float* __restrict__ W1) {
    extern __shared__ float sm[];
    float* wb0 = sm;
    float* wb1 = sm + WBUF;
    float* a1s = sm + 2 * WBUF;
    float* v1s = a1s + 6208;

    const int tid  = threadIdx.x;
    const int lane = tid & 31;
    const int wid  = tid >> 5;
    const int wm   = wid & 3;    // m-warp: rows 16*wm..16*wm+15 (+8 group)
    const int wn   = wid >> 2;   // n-warp: cols 48*wn..48*wn+47
    const int gid  = lane >> 2;
    const int tig  = lane & 3;
    const int b0   = wm * 16 + gid;
    const int nbase = wn * 48;

    for (int i = tid; i < 6208; i += 256) { a1s[i] = g_a1[i]; v1s[i] = g_v1[i]; }
    // zero pad rows 97..103 of both buffers (k-tail reads them; t1 frag there = 0)
    for (int i = tid; i < 7 * LDSW; i += 256) {
        wb0[97 * LDSW + i] = 0.f;
        wb1[97 * LDSW + i] = 0.f;
    }

    // persistent t1 A-fragments (13 k-steps of 8 covering t = 0..96, padded)
    float t1f[13][4];
#pragma unroll
    for (int ks = 0; ks < 13; ks++) {
        int ta = ks * 8 + tig;
        int tb = ta + 4;
        t1f[ks][0] = (ta < 97) ? g_t1[b0 * 97 + ta] : 0.f;
        t1f[ks][1] = (ta < 97) ? g_t1[(b0 + 8) * 97 + ta] : 0.f;
        t1f[ks][2] = (tb < 97) ? g_t1[b0 * 97 + tb] : 0.f;
        t1f[ks][3] = (tb < 97) ? g_t1[(b0 + 8) * 97 + tb] : 0.f;
    }

    float Y[6][4];
#pragma unroll
    for (int j = 0; j < 6; j++) { Y[j][0] = Y[j][1] = Y[j][2] = Y[j][3] = 0.f; }

    const int bk = blockIdx.x;
    // 9409 = 152*61 + 137 : first 137 blocks take 62 chunks
    const int cstart = (bk < 137) ? bk * 62 : bk * 61 + 137;
    const int ccnt   = (bk < 137) ? 62 : 61;

    float4 stg[10];
    // prologue
    stage_ldg(stg, W1, cstart, tid);
    stage_sts(wb0, stg, tid);
    __syncthreads();

    for (int ci = 0; ci < ccnt; ci++) {
        const float* cur = (ci & 1) ? wb1 : wb0;
        float* nxt       = (ci & 1) ? wb0 : wb1;
        const int av = cstart + ci;
        const bool hn = (ci + 1 < ccnt);

        if (hn) stage_ldg(stg, W1, av + 1, tid);   // overlap with compute

        const int ca = av / 97;
        const int cv = av - ca * 97;
        const float m0r = a1s[b0 * 97 + ca] * v1s[b0 * 97 + cv];
        const float m1r = a1s[(b0 + 8) * 97 + ca] * v1s[(b0 + 8) * 97 + cv];

#pragma unroll
        for (int ks = 0; ks < 13; ks++) {
            const uint32_t A0 = f2tf32u(m0r * t1f[ks][0]);
            const uint32_t A1 = f2tf32u(m1r * t1f[ks][1]);
            const uint32_t A2 = f2tf32u(m0r * t1f[ks][2]);
            const uint32_t A3 = f2tf32u(m1r * t1f[ks][3]);
            const float* bp  = cur + (ks * 8 + tig) * LDSW + nbase + gid;
            const float* bp4 = bp + 4 * LDSW;
#pragma unroll
            for (int j = 0; j < 6; j++) {
                uint32_t B0 = __float_as_uint(bp[8 * j]);
                uint32_t B1 = __float_as_uint(bp4[8 * j]);
                mma_tf32(Y[j], A0, A1, A2, A3, B0, B1);
            }
        }

        if (hn) stage_sts(nxt, stg, tid);
        __syncthreads();
    }

    // write fp32 partials [bk][b][h]
    float* dst = g_part + (size_t)bk * (BDIM * HDIM);
#pragma unroll
    for (int j = 0; j < 6; j++) {
        int h = nbase + 8 * j + 2 * tig;
        *reinterpret_cast<float2*>(dst + b0 * HDIM + h) =
            make_float2(Y[j][0], Y[j][1]);
        *reinterpret_cast<float2*>(dst + (b0 + 8) * HDIM + h) =
            make_float2(Y[j][2], Y[j][3]);
    }
}

// ---------------------------------------------------------------------------
// Kernel 3: reduce partials + bias/relu + W2 + heads. One block per batch row.
// 384 threads: (h, g) with g in [0,4) splitting the 152-partial reduction.
// out layout: features[64*96] | emos[64*6] | vals[64*1] | sents[64*3] | interloss
// ---------------------------------------------------------------------------
__global__ void __launch_bounds__(384) tfn_tail(
    const float* __restrict__ b1, const float* __restrict__ W2,
    const float* __restrict__ b2,
    const float* __restrict__ Wo1, const float* __restrict__ bo1,
    const float* __restrict__ Wo2, const float* __restrict__ bo2,
    const float* __restrict__ Wo3, const float* __restrict__ bo3,
    float* __restrict__ out) {
    __shared__ float ps[384];
    __shared__ float yr[HDIM];
    __shared__ float fs[HDIM];
    const int b   = blockIdx.x;
    const int tid = threadIdx.x;
    const int h   = tid % 96;
    const int g   = tid / 96;   // 0..3

    float acc = 0.f;
#pragma unroll 8
    for (int p = g; p < NBLK; p += 4)
        acc += g_part[(size_t)p * (BDIM * HDIM) + b * HDIM + h];
    ps[tid] = acc;
    __syncthreads();

    if (g == 0) {
        float r = b1[h] + ((ps[h] + ps[h + 96]) + (ps[h + 192] + ps[h + 288]));
        yr[h] = fmaxf(r, 0.f);
    }
    __syncthreads();

    if (g == 0) {
        float f = b2[h];
#pragma unroll 8
        for (int k = 0; k < HDIM; k++) f += yr[k] * W2[k * HDIM + h];
        f = fmaxf(f, 0.f);
        fs[h] = f;
        out[b * HDIM + h] = f;
    }
    __syncthreads();

    if (tid < 6) {
        float a = bo1[tid];
        for (int k = 0; k < HDIM; k++) a += fs[k] * Wo1[k * 6 + tid];
        out[6144 + b * 6 + tid] = a;
    } else if (tid == 6) {
        float a = bo2[0];
        for (int k = 0; k < HDIM; k++) a += fs[k] * Wo2[k];
        out[6528 + b] = a;
    } else if (tid < 10) {
        int o = tid - 7;
        float a = bo3[o];
        for (int k = 0; k < HDIM; k++) a += fs[k] * Wo3[k * 3 + o];
        out[6592 + b * 3 + o] = a;
    }
    if (b == 0 && tid == 95) out[6784] = 0.f;  // interloss
}

// ---------------------------------------------------------------------------

extern "C" void kernel_launch(void* const* d_in, const int* in_sizes, int n_in,
                              void* d_out, int out_size) {
    (void)in_sizes; (void)n_in; (void)out_size;
    const float* audios = (const float*)d_in[0];
    const float* texts  = (const float*)d_in[1];
    const float* videos = (const float*)d_in[2];
    const float* Wa  = (const float*)d_in[3];
    const float* ba  = (const float*)d_in[4];
    const float* Wt  = (const float*)d_in[5];
    const float* bt  = (const float*)d_in[6];
    const float* Wv  = (const float*)d_in[7];
    const float* bv  = (const float*)d_in[8];
    const float* W1  = (const float*)d_in[9];
    const float* b1  = (const float*)d_in[10];
    const float* W2  = (const float*)d_in[11];
    const float* b2  = (const float*)d_in[12];
    const float* Wo1 = (const float*)d_in[13];
    const float* bo1 = (const float*)d_in[14];
    const float* Wo2 = (const float*)d_in[15];
    const float* bo2 = (const float*)d_in[16];
    const float* Wo3 = (const float*)d_in[17];
    const float* bo3 = (const float*)d_in[18];
    float* out = (float*)d_out;

    cudaFuncSetAttribute(tfn_main, cudaFuncAttributeMaxDynamicSharedMemorySize,
                         SMEM_FLOATS * 4);

    tfn_enc<<<dim3(64, 3), 384>>>(audios, texts, videos, Wa, ba, Wt, bt, Wv, bv);
    tfn_main<<<NBLK, 256, SMEM_FLOATS * 4>>>(W1);
    tfn_tail<<<64, 384>>>(b1, W2, b2, Wo1, bo1, Wo2, bo2, Wo3, bo3, out);
}

// round 3
// speedup vs baseline: 1.6034x; 1.1405x over previous
#include <cuda_runtime.h>
#include <cstdint>

// ---------------------------------------------------------------------------
// TFN forward:
//   a1/v1/t1 = [1, relu(x @ W + b)]            (B=64, H=96 -> 97 cols each)
//   y1 = relu( einsum('ba,bv,bt->b(avt)') @ W1 + b1 )   <-- 350 MB W1, dominant
//   features = relu(y1 @ W2 + b2)
//   heads: features @ Wo{1,2,3} + bo{1,2,3};  interloss = 0
//
// R3 changes: enc was still latency-bound (29.9us, occ capped at 21.7% by
// grid shape). enc now 768 thr = 96h x 8 K-slices; tail 768 thr = 96h x 8
// partial-slices. tfn_main unchanged (at legacy-HMMA rate floor ~100us;
// tcgen05 rewrite is the next step).
// ---------------------------------------------------------------------------

#define NBLK   152
#define CHUNKS 9409          // 97*97 (a,v) pairs
#define BDIM   64
#define HDIM   96
#define LDSW   104           // smem row stride in floats
#define WBUF   (LDSW * 104)  // one W1 chunk buffer (104 rows x 104 floats)
#define SMEM_FLOATS (2*WBUF + 2*6208)

__device__ float g_a1[BDIM * 97];
__device__ float g_v1[BDIM * 97];
__device__ float g_t1[BDIM * 97];
__device__ float g_part[NBLK * BDIM * HDIM];

// ---------------------------------------------------------------------------

__device__ __forceinline__ float f2tf32f(float x) {
    uint32_t r;
    asm("cvt.rna.tf32.f32 %0, %1;" : "=r"(r) : "f"(x));
    return __uint_as_float(r);
}
__device__ __forceinline__ uint32_t f2tf32u(float x) {
    uint32_t r;
    asm("cvt.rna.tf32.f32 %0, %1;" : "=r"(r) : "f"(x));
    return r;
}

__device__ __forceinline__ void mma_tf32(float c[4],
                                         uint32_t a0, uint32_t a1,
                                         uint32_t a2, uint32_t a3,
                                         uint32_t b0, uint32_t b1) {
    asm volatile(
        "mma.sync.aligned.m16n8k8.row.col.f32.tf32.tf32.f32 "
        "{%0,%1,%2,%3}, {%4,%5,%6,%7}, {%8,%9}, {%0,%1,%2,%3};"
        : "+f"(c[0]), "+f"(c[1]), "+f"(c[2]), "+f"(c[3])
        : "r"(a0), "r"(a1), "r"(a2), "r"(a3), "r"(b0), "r"(b1));
}

// 97*96 = 9312 floats = 2328 float4 per chunk. 256 threads: 9 each + 24 extra.
__device__ __forceinline__ void stage_ldg(float4* stg,
                                          const float* __restrict__ W1,
                                          int av, int tid) {
    const float4* src = reinterpret_cast<const float4*>(W1 + (size_t)av * 9312);
#pragma unroll
    for (int j = 0; j < 9; j++) stg[j] = src[tid + j * 256];
    if (tid < 24) stg[9] = src[2304 + tid];
}

__device__ __forceinline__ void stage_sts(float* buf, const float4* stg, int tid) {
#pragma unroll
    for (int j = 0; j < 9; j++) {
        int q = tid + j * 256;
        int e = q * 4;
        int t = e / 96;
        int c = e - t * 96;
        float4 v = stg[j], o;
        o.x = f2tf32f(v.x); o.y = f2tf32f(v.y);
        o.z = f2tf32f(v.z); o.w = f2tf32f(v.w);
        *reinterpret_cast<float4*>(buf + t * LDSW + c) = o;
    }
    if (tid < 24) {
        int q = 2304 + tid;
        int e = q * 4;
        int t = e / 96;
        int c = e - t * 96;
        float4 v = stg[9], o;
        o.x = f2tf32f(v.x); o.y = f2tf32f(v.y);
        o.z = f2tf32f(v.z); o.w = f2tf32f(v.w);
        *reinterpret_cast<float4*>(buf + t * LDSW + c) = o;
    }
}

// ---------------------------------------------------------------------------
// Kernel 1: encoders. grid (64 batch, 3 mods), 768 threads = 96 h x 8 slices.
// x row staged in smem; 8 partial dot products reduced through smem.
// ---------------------------------------------------------------------------
__global__ void __launch_bounds__(768) tfn_enc(
    const float* __restrict__ audios, const float* __restrict__ texts,
    const float* __restrict__ videos,
    const float* __restrict__ Wa, const float* __restrict__ ba,
    const float* __restrict__ Wt, const float* __restrict__ bt,
    const float* __restrict__ Wv, const float* __restrict__ bv) {
    const int b   = blockIdx.x;
    const int mod = blockIdx.y;
    const int tid = threadIdx.x;

    const float* x; const float* W; const float* bias; float* out; int K;
    if (mod == 0)      { x = audios; W = Wa; bias = ba; out = g_a1; K = 512; }
    else if (mod == 1) { x = texts;  W = Wt; bias = bt; out = g_t1; K = 1024; }
    else               { x = videos; W = Wv; bias = bv; out = g_v1; K = 512; }

    __shared__ float xs[1024];
    __shared__ float ps[768];

    const float* xb = x + (size_t)b * K;
    for (int i = tid; i < K; i += 768) xs[i] = xb[i];
    __syncthreads();

    const int h  = tid % 96;
    const int g  = tid / 96;           // 0..7
    const int kq = K >> 3;             // 64 or 128
    const int k0 = g * kq;

    float acc = 0.f;
#pragma unroll 8
    for (int k = k0; k < k0 + kq; k++)
        acc += xs[k] * W[k * HDIM + h];
    ps[tid] = acc;
    __syncthreads();

    if (g == 0) {
        float r = bias[h];
#pragma unroll
        for (int i = 0; i < 8; i++) r += ps[h + 96 * i];
        out[b * 97 + 1 + h] = fmaxf(r, 0.f);
        if (h == 0) out[b * 97] = 1.f;
    }
}

// ---------------------------------------------------------------------------
// Kernel 2: main fused trilinear GEMM (y1 partials, pre-bias/relu)
//   grid = 152 CTAs x 256 threads, 1 CTA/SM, dynamic smem 136 KB
// ---------------------------------------------------------------------------
__global__ void __launch_bounds__(256, 1) tfn_main(const float* __restrict__ W1) {
    extern __shared__ float sm[];
    float* wb0 = sm;
    float* wb1 = sm + WBUF;
    float* a1s = sm + 2 * WBUF;
    float* v1s = a1s + 6208;

    const int tid  = threadIdx.x;
    const int lane = tid & 31;
    const int wid  = tid >> 5;
    const int wm   = wid & 3;    // m-warp: rows 16*wm..16*wm+15 (+8 group)
    const int wn   = wid >> 2;   // n-warp: cols 48*wn..48*wn+47
    const int gid  = lane >> 2;
    const int tig  = lane & 3;
    const int b0   = wm * 16 + gid;
    const int nbase = wn * 48;

    for (int i = tid; i < 6208; i += 256) { a1s[i] = g_a1[i]; v1s[i] = g_v1[i]; }
    // zero pad rows 97..103 of both buffers (k-tail reads them; t1 frag there = 0)
    for (int i = tid; i < 7 * LDSW; i += 256) {
        wb0[97 * LDSW + i] = 0.f;
        wb1[97 * LDSW + i] = 0.f;
    }

    // persistent t1 A-fragments (13 k-steps of 8 covering t = 0..96, padded)
    float t1f[13][4];
#pragma unroll
    for (int ks = 0; ks < 13; ks++) {
        int ta = ks * 8 + tig;
        int tb = ta + 4;
        t1f[ks][0] = (ta < 97) ? g_t1[b0 * 97 + ta] : 0.f;
        t1f[ks][1] = (ta < 97) ? g_t1[(b0 + 8) * 97 + ta] : 0.f;
        t1f[ks][2] = (tb < 97) ? g_t1[b0 * 97 + tb] : 0.f;
        t1f[ks][3] = (tb < 97) ? g_t1[(b0 + 8) * 97 + tb] : 0.f;
    }

    float Y[6][4];
#pragma unroll
    for (int j = 0; j < 6; j++) { Y[j][0] = Y[j][1] = Y[j][2] = Y[j][3] = 0.f; }

    const int bk = blockIdx.x;
    // 9409 = 152*61 + 137 : first 137 blocks take 62 chunks
    const int cstart = (bk < 137) ? bk * 62 : bk * 61 + 137;
    const int ccnt   = (bk < 137) ? 62 : 61;

    float4 stg[10];
    // prologue
    stage_ldg(stg, W1, cstart, tid);
    stage_sts(wb0, stg, tid);
    __syncthreads();

    for (int ci = 0; ci < ccnt; ci++) {
        const float* cur = (ci & 1) ? wb1 : wb0;
        float* nxt       = (ci & 1) ? wb0 : wb1;
        const int av = cstart + ci;
        const bool hn = (ci + 1 < ccnt);

        if (hn) stage_ldg(stg, W1, av + 1, tid);   // overlap with compute

        const int ca = av / 97;
        const int cv = av - ca * 97;
        const float m0r = a1s[b0 * 97 + ca] * v1s[b0 * 97 + cv];
        const float m1r = a1s[(b0 + 8) * 97 + ca] * v1s[(b0 + 8) * 97 + cv];

#pragma unroll
        for (int ks = 0; ks < 13; ks++) {
            const uint32_t A0 = f2tf32u(m0r * t1f[ks][0]);
            const uint32_t A1 = f2tf32u(m1r * t1f[ks][1]);
            const uint32_t A2 = f2tf32u(m0r * t1f[ks][2]);
            const uint32_t A3 = f2tf32u(m1r * t1f[ks][3]);
            const float* bp  = cur + (ks * 8 + tig) * LDSW + nbase + gid;
            const float* bp4 = bp + 4 * LDSW;
#pragma unroll
            for (int j = 0; j < 6; j++) {
                uint32_t B0 = __float_as_uint(bp[8 * j]);
                uint32_t B1 = __float_as_uint(bp4[8 * j]);
                mma_tf32(Y[j], A0, A1, A2, A3, B0, B1);
            }
        }

        if (hn) stage_sts(nxt, stg, tid);
        __syncthreads();
    }

    // write fp32 partials [bk][b][h]
    float* dst = g_part + (size_t)bk * (BDIM * HDIM);
#pragma unroll
    for (int j = 0; j < 6; j++) {
        int h = nbase + 8 * j + 2 * tig;
        *reinterpret_cast<float2*>(dst + b0 * HDIM + h) =
            make_float2(Y[j][0], Y[j][1]);
        *reinterpret_cast<float2*>(dst + (b0 + 8) * HDIM + h) =
            make_float2(Y[j][2], Y[j][3]);
    }
}

// ---------------------------------------------------------------------------
// Kernel 3: reduce partials + bias/relu + W2 + heads. One block per batch row.
// 768 threads: (h, g) with g in [0,8) splitting the 152-partial reduction.
// out layout: features[64*96] | emos[64*6] | vals[64*1] | sents[64*3] | interloss
// ---------------------------------------------------------------------------
__global__ void __launch_bounds__(768) tfn_tail(
    const float* __restrict__ b1, const float* __restrict__ W2,
    const float* __restrict__ b2,
    const float* __restrict__ Wo1, const float* __restrict__ bo1,
    const float* __restrict__ Wo2, const float* __restrict__ bo2,
    const float* __restrict__ Wo3, const float* __restrict__ bo3,
    float* __restrict__ out) {
    __shared__ float ps[768];
    __shared__ float yr[HDIM];
    __shared__ float fs[HDIM];
    const int b   = blockIdx.x;
    const int tid = threadIdx.x;
    const int h   = tid % 96;
    const int g   = tid / 96;   // 0..7

    float acc = 0.f;
#pragma unroll 4
    for (int p = g; p < NBLK; p += 8)
        acc += g_part[(size_t)p * (BDIM * HDIM) + b * HDIM + h];
    ps[tid] = acc;
    __syncthreads();

    if (g == 0) {
        float r = b1[h];
#pragma unroll
        for (int i = 0; i < 8; i++) r += ps[h + 96 * i];
        yr[h] = fmaxf(r, 0.f);
    }
    __syncthreads();

    if (g == 0) {
        float f = b2[h];
#pragma unroll 8
        for (int k = 0; k < HDIM; k++) f += yr[k] * W2[k * HDIM + h];
        f = fmaxf(f, 0.f);
        fs[h] = f;
        out[b * HDIM + h] = f;
    }
    __syncthreads();

    if (tid < 6) {
        float a = bo1[tid];
        for (int k = 0; k < HDIM; k++) a += fs[k] * Wo1[k * 6 + tid];
        out[6144 + b * 6 + tid] = a;
    } else if (tid == 6) {
        float a = bo2[0];
        for (int k = 0; k < HDIM; k++) a += fs[k] * Wo2[k];
        out[6528 + b] = a;
    } else if (tid < 10) {
        int o = tid - 7;
        float a = bo3[o];
        for (int k = 0; k < HDIM; k++) a += fs[k] * Wo3[k * 3 + o];
        out[6592 + b * 3 + o] = a;
    }
    if (b == 0 && tid == 95) out[6784] = 0.f;  // interloss
}

// ---------------------------------------------------------------------------

extern "C" void kernel_launch(void* const* d_in, const int* in_sizes, int n_in,
                              void* d_out, int out_size) {
    (void)in_sizes; (void)n_in; (void)out_size;
    const float* audios = (const float*)d_in[0];
    const float* texts  = (const float*)d_in[1];
    const float* videos = (const float*)d_in[2];
    const float* Wa  = (const float*)d_in[3];
    const float* ba  = (const float*)d_in[4];
    const float* Wt  = (const float*)d_in[5];
    const float* bt  = (const float*)d_in[6];
    const float* Wv  = (const float*)d_in[7];
    const float* bv  = (const float*)d_in[8];
    const float* W1  = (const float*)d_in[9];
    const float* b1  = (const float*)d_in[10];
    const float* W2  = (const float*)d_in[11];
    const float* b2  = (const float*)d_in[12];
    const float* Wo1 = (const float*)d_in[13];
    const float* bo1 = (const float*)d_in[14];
    const float* Wo2 = (const float*)d_in[15];
    const float* bo2 = (const float*)d_in[16];
    const float* Wo3 = (const float*)d_in[17];
    const float* bo3 = (const float*)d_in[18];
    float* out = (float*)d_out;

    cudaFuncSetAttribute(tfn_main, cudaFuncAttributeMaxDynamicSharedMemorySize,
                         SMEM_FLOATS * 4);

    tfn_enc<<<dim3(64, 3), 768>>>(audios, texts, videos, Wa, ba, Wt, bt, Wv, bv);
    tfn_main<<<NBLK, 256, SMEM_FLOATS * 4>>>(W1);
    tfn_tail<<<64, 768>>>(b1, W2, b2, Wo1, bo1, Wo2, bo2, Wo3, bo3, out);
}

// round 4
// speedup vs baseline: 1.9101x; 1.1913x over previous
#include <cuda_runtime.h>
#include <cuda_fp16.h>
#include <cstdint>

// ---------------------------------------------------------------------------
// TFN forward. R4 change: main trilinear GEMM engine switched from tf32
// m16n8k8 (+scalar LDS feeds, issue-bound ~2800 cyc/SMSP/chunk) to fp16
// m16n8k16 with ldmatrix.x4.trans B feeds (~1000 cyc/SMSP/chunk), fp32
// accumulate. W1 staged to smem as fp16 (halves SMEM traffic). Structure
// (152 CTAs, 256 thr, double buffer, 4x2 warp grid) unchanged.
// ---------------------------------------------------------------------------

#define NBLK   152
#define BDIM   64
#define HDIM   96
#define LDH    104            // smem B row stride in halfs (208 B, LDSM conflict-free)
#define KROWS  112            // 97 data rows + 15 zero pad (7 k16 steps)
#define WBUFH  (KROWS * LDH)  // halfs per buffer
#define SMEM_BYTES (2*WBUFH*2 + 2*6208*4)

__device__ float g_a1[BDIM * 97];
__device__ float g_v1[BDIM * 97];
__device__ float g_t1[BDIM * 97];
__device__ float g_part[NBLK * BDIM * HDIM];

// ---------------------------------------------------------------------------

__device__ __forceinline__ uint32_t h2u(__half2 h) {
    return *reinterpret_cast<uint32_t*>(&h);
}

__device__ __forceinline__ void mma_f16(float c[4],
                                        uint32_t a0, uint32_t a1,
                                        uint32_t a2, uint32_t a3,
                                        uint32_t b0, uint32_t b1) {
    asm volatile(
        "mma.sync.aligned.m16n8k16.row.col.f32.f16.f16.f32 "
        "{%0,%1,%2,%3}, {%4,%5,%6,%7}, {%8,%9}, {%0,%1,%2,%3};"
        : "+f"(c[0]), "+f"(c[1]), "+f"(c[2]), "+f"(c[3])
        : "r"(a0), "r"(a1), "r"(a2), "r"(a3), "r"(b0), "r"(b1));
}

struct __align__(8) H4 { __half2 a, b; };

// 97*96 = 9312 floats = 2328 float4 per chunk. 256 threads: 9 each + 24 extra.
__device__ __forceinline__ void stage_ldg(float4* stg,
                                          const float* __restrict__ W1,
                                          int av, int tid) {
    const float4* src = reinterpret_cast<const float4*>(W1 + (size_t)av * 9312);
#pragma unroll
    for (int j = 0; j < 9; j++) stg[j] = src[tid + j * 256];
    if (tid < 24) stg[9] = src[2304 + tid];
}

__device__ __forceinline__ void stage_sts(__half* buf, const float4* stg, int tid) {
#pragma unroll
    for (int j = 0; j < 9; j++) {
        int q = tid + j * 256;
        int e = q * 4;
        int t = e / 96;
        int c = e - t * 96;
        float4 v = stg[j];
        H4 o;
        o.a = __floats2half2_rn(v.x, v.y);
        o.b = __floats2half2_rn(v.z, v.w);
        *reinterpret_cast<H4*>(buf + t * LDH + c) = o;
    }
    if (tid < 24) {
        int q = 2304 + tid;
        int e = q * 4;
        int t = e / 96;
        int c = e - t * 96;
        float4 v = stg[9];
        H4 o;
        o.a = __floats2half2_rn(v.x, v.y);
        o.b = __floats2half2_rn(v.z, v.w);
        *reinterpret_cast<H4*>(buf + t * LDH + c) = o;
    }
}

// ---------------------------------------------------------------------------
// Kernel 1: encoders. grid (64 batch, 3 mods), 768 threads = 96 h x 8 slices.
// ---------------------------------------------------------------------------
__global__ void __launch_bounds__(768) tfn_enc(
    const float* __restrict__ audios, const float* __restrict__ texts,
    const float* __restrict__ videos,
    const float* __restrict__ Wa, const float* __restrict__ ba,
    const float* __restrict__ Wt, const float* __restrict__ bt,
    const float* __restrict__ Wv, const float* __restrict__ bv) {
    const int b   = blockIdx.x;
    const int mod = blockIdx.y;
    const int tid = threadIdx.x;

    const float* x; const float* W; const float* bias; float* out; int K;
    if (mod == 0)      { x = audios; W = Wa; bias = ba; out = g_a1; K = 512; }
    else if (mod == 1) { x = texts;  W = Wt; bias = bt; out = g_t1; K = 1024; }
    else               { x = videos; W = Wv; bias = bv; out = g_v1; K = 512; }

    __shared__ float xs[1024];
    __shared__ float ps[768];

    const float* xb = x + (size_t)b * K;
    for (int i = tid; i < K; i += 768) xs[i] = xb[i];
    __syncthreads();

    const int h  = tid % 96;
    const int g  = tid / 96;           // 0..7
    const int kq = K >> 3;             // 64 or 128
    const int k0 = g * kq;

    float acc = 0.f;
#pragma unroll 8
    for (int k = k0; k < k0 + kq; k++)
        acc += xs[k] * W[k * HDIM + h];
    ps[tid] = acc;
    __syncthreads();

    if (g == 0) {
        float r = bias[h];
#pragma unroll
        for (int i = 0; i < 8; i++) r += ps[h + 96 * i];
        out[b * 97 + 1 + h] = fmaxf(r, 0.f);
        if (h == 0) out[b * 97] = 1.f;
    }
}

// ---------------------------------------------------------------------------
// Kernel 2: main fused trilinear GEMM (y1 partials, pre-bias/relu)
//   grid = 152 CTAs x 256 threads, 1 CTA/SM
// ---------------------------------------------------------------------------
__global__ void __launch_bounds__(256, 1) tfn_main(const float* __restrict__ W1) {
    extern __shared__ char smx[];
    __half* wb0 = reinterpret_cast<__half*>(smx);
    __half* wb1 = wb0 + WBUFH;
    float*  a1s = reinterpret_cast<float*>(wb1 + WBUFH);
    float*  v1s = a1s + 6208;

    const int tid  = threadIdx.x;
    const int lane = tid & 31;
    const int wid  = tid >> 5;
    const int wm   = wid & 3;    // m-warp: batch rows 16*wm..16*wm+15
    const int wn   = wid >> 2;   // n-warp: cols 48*wn..48*wn+47
    const int gid  = lane >> 2;
    const int tig  = lane & 3;
    const int b0   = wm * 16 + gid;
    const int nbase = wn * 48;

    for (int i = tid; i < 6208; i += 256) { a1s[i] = g_a1[i]; v1s[i] = g_v1[i]; }
    // zero pad rows 97..111 of both buffers (k-tail; A frags there are 0 too)
    {
        uint32_t* z0 = reinterpret_cast<uint32_t*>(wb0 + 97 * LDH);
        uint32_t* z1 = reinterpret_cast<uint32_t*>(wb1 + 97 * LDH);
        for (int i = tid; i < (15 * LDH) / 2; i += 256) { z0[i] = 0; z1[i] = 0; }
    }

    // persistent t1 A-fragments as half2 pairs: 7 k16-steps
    __half2 t1f[7][4];
#pragma unroll
    for (int ks = 0; ks < 7; ks++) {
        int ka = ks * 16 + 2 * tig;
        int kb = ka + 8;
        float x0 = (ka     < 97) ? g_t1[b0 * 97 + ka]           : 0.f;
        float x1 = (ka + 1 < 97) ? g_t1[b0 * 97 + ka + 1]       : 0.f;
        float y0 = (ka     < 97) ? g_t1[(b0 + 8) * 97 + ka]     : 0.f;
        float y1 = (ka + 1 < 97) ? g_t1[(b0 + 8) * 97 + ka + 1] : 0.f;
        float x2 = (kb     < 97) ? g_t1[b0 * 97 + kb]           : 0.f;
        float x3 = (kb + 1 < 97) ? g_t1[b0 * 97 + kb + 1]       : 0.f;
        float y2 = (kb     < 97) ? g_t1[(b0 + 8) * 97 + kb]     : 0.f;
        float y3 = (kb + 1 < 97) ? g_t1[(b0 + 8) * 97 + kb + 1] : 0.f;
        t1f[ks][0] = __floats2half2_rn(x0, x1);
        t1f[ks][1] = __floats2half2_rn(y0, y1);
        t1f[ks][2] = __floats2half2_rn(x2, x3);
        t1f[ks][3] = __floats2half2_rn(y2, y3);
    }

    float Y[6][4];
#pragma unroll
    for (int j = 0; j < 6; j++) { Y[j][0] = Y[j][1] = Y[j][2] = Y[j][3] = 0.f; }

    const int bk = blockIdx.x;
    // 9409 = 152*61 + 137 : first 137 blocks take 62 chunks
    const int cstart = (bk < 137) ? bk * 62 : bk * 61 + 137;
    const int ccnt   = (bk < 137) ? 62 : 61;

    // per-thread LDSM row pointer offsets (in halfs)
    const int lrow = lane & 15;          // k row within k16 step
    const int lcol = (lane >> 4) * 8;    // 0 or 8 within n16 block

    float4 stg[10];
    stage_ldg(stg, W1, cstart, tid);
    stage_sts(wb0, stg, tid);
    __syncthreads();

    for (int ci = 0; ci < ccnt; ci++) {
        const __half* cur = (ci & 1) ? wb1 : wb0;
        __half* nxt       = (ci & 1) ? wb0 : wb1;
        const int av = cstart + ci;
        const bool hn = (ci + 1 < ccnt);

        if (hn) stage_ldg(stg, W1, av + 1, tid);   // overlap with compute

        const int ca = av / 97;
        const int cv = av - ca * 97;
        const __half2 m0h = __float2half2_rn(a1s[b0 * 97 + ca] * v1s[b0 * 97 + cv]);
        const __half2 m1h = __float2half2_rn(a1s[(b0 + 8) * 97 + ca] * v1s[(b0 + 8) * 97 + cv]);

#pragma unroll
        for (int ks = 0; ks < 7; ks++) {
            const uint32_t A0 = h2u(__hmul2(m0h, t1f[ks][0]));
            const uint32_t A1 = h2u(__hmul2(m1h, t1f[ks][1]));
            const uint32_t A2 = h2u(__hmul2(m0h, t1f[ks][2]));
            const uint32_t A3 = h2u(__hmul2(m1h, t1f[ks][3]));
            const __half* rowp = cur + (ks * 16 + lrow) * LDH + nbase + lcol;
#pragma unroll
            for (int j3 = 0; j3 < 3; j3++) {
                uint32_t saddr =
                    (uint32_t)__cvta_generic_to_shared(rowp + 16 * j3);
                uint32_t B0, B1, B2, B3;
                asm volatile(
                    "ldmatrix.sync.aligned.m8n8.x4.trans.shared.b16 "
                    "{%0,%1,%2,%3}, [%4];"
                    : "=r"(B0), "=r"(B1), "=r"(B2), "=r"(B3) : "r"(saddr));
                mma_f16(Y[2 * j3],     A0, A1, A2, A3, B0, B1);
                mma_f16(Y[2 * j3 + 1], A0, A1, A2, A3, B2, B3);
            }
        }

        if (hn) stage_sts(nxt, stg, tid);
        __syncthreads();
    }

    // write fp32 partials [bk][b][h]
    float* dst = g_part + (size_t)bk * (BDIM * HDIM);
#pragma unroll
    for (int j = 0; j < 6; j++) {
        int h = nbase + 8 * j + 2 * tig;
        *reinterpret_cast<float2*>(dst + b0 * HDIM + h) =
            make_float2(Y[j][0], Y[j][1]);
        *reinterpret_cast<float2*>(dst + (b0 + 8) * HDIM + h) =
            make_float2(Y[j][2], Y[j][3]);
    }
}

// ---------------------------------------------------------------------------
// Kernel 3: reduce partials + bias/relu + W2 + heads. One block per batch row.
// ---------------------------------------------------------------------------
__global__ void __launch_bounds__(768) tfn_tail(
    const float* __restrict__ b1, const float* __restrict__ W2,
    const float* __restrict__ b2,
    const float* __restrict__ Wo1, const float* __restrict__ bo1,
    const float* __restrict__ Wo2, const float* __restrict__ bo2,
    const float* __restrict__ Wo3, const float* __restrict__ bo3,
    float* __restrict__ out) {
    __shared__ float ps[768];
    __shared__ float yr[HDIM];
    __shared__ float fs[HDIM];
    const int b   = blockIdx.x;
    const int tid = threadIdx.x;
    const int h   = tid % 96;
    const int g   = tid / 96;   // 0..7

    float acc = 0.f;
#pragma unroll 4
    for (int p = g; p < NBLK; p += 8)
        acc += g_part[(size_t)p * (BDIM * HDIM) + b * HDIM + h];
    ps[tid] = acc;
    __syncthreads();

    if (g == 0) {
        float r = b1[h];
#pragma unroll
        for (int i = 0; i < 8; i++) r += ps[h + 96 * i];
        yr[h] = fmaxf(r, 0.f);
    }
    __syncthreads();

    if (g == 0) {
        float f = b2[h];
#pragma unroll 8
        for (int k = 0; k < HDIM; k++) f += yr[k] * W2[k * HDIM + h];
        f = fmaxf(f, 0.f);
        fs[h] = f;
        out[b * HDIM + h] = f;
    }
    __syncthreads();

    if (tid < 6) {
        float a = bo1[tid];
        for (int k = 0; k < HDIM; k++) a += fs[k] * Wo1[k * 6 + tid];
        out[6144 + b * 6 + tid] = a;
    } else if (tid == 6) {
        float a = bo2[0];
        for (int k = 0; k < HDIM; k++) a += fs[k] * Wo2[k];
        out[6528 + b] = a;
    } else if (tid < 10) {
        int o = tid - 7;
        float a = bo3[o];
        for (int k = 0; k < HDIM; k++) a += fs[k] * Wo3[k * 3 + o];
        out[6592 + b * 3 + o] = a;
    }
    if (b == 0 && tid == 95) out[6784] = 0.f;  // interloss
}

// ---------------------------------------------------------------------------

extern "C" void kernel_launch(void* const* d_in, const int* in_sizes, int n_in,
                              void* d_out, int out_size) {
    (void)in_sizes; (void)n_in; (void)out_size;
    const float* audios = (const float*)d_in[0];
    const float* texts  = (const float*)d_in[1];
    const float* videos = (const float*)d_in[2];
    const float* Wa  = (const float*)d_in[3];
    const float* ba  = (const float*)d_in[4];
    const float* Wt  = (const float*)d_in[5];
    const float* bt  = (const float*)d_in[6];
    const float* Wv  = (const float*)d_in[7];
    const float* bv  = (const float*)d_in[8];
    const float* W1  = (const float*)d_in[9];
    const float* b1  = (const float*)d_in[10];
    const float* W2  = (const float*)d_in[11];
    const float* b2  = (const float*)d_in[12];
    const float* Wo1 = (const float*)d_in[13];
    const float* bo1 = (const float*)d_in[14];
    const float* Wo2 = (const float*)d_in[15];
    const float* bo2 = (const float*)d_in[16];
    const float* Wo3 = (const float*)d_in[17];
    const float* bo3 = (const float*)d_in[18];
    float* out = (float*)d_out;

    cudaFuncSetAttribute(tfn_main, cudaFuncAttributeMaxDynamicSharedMemorySize,
                         SMEM_BYTES);

    tfn_enc<<<dim3(64, 3), 768>>>(audios, texts, videos, Wa, ba, Wt, bt, Wv, bv);
    tfn_main<<<NBLK, 256, SMEM_BYTES>>>(W1);
    tfn_tail<<<64, 768>>>(b1, W2, b2, Wo1, bo1, Wo2, bo2, Wo3, bo3, out);
}